// round 5
// baseline (speedup 1.0000x reference)
#include <cuda_runtime.h>
#include <math.h>
#include <stdint.h>

#define D_MODEL 768
#define VOCAB   32128
#define NTOK    2048
#define NTILES_N 251           // VOCAB / 128
#define BM 256
#define BN 128
#define BKF 32                 // k-floats per chunk
#define NCHUNK (D_MODEL / BKF) // 24
#define ASTR 36                // smem row stride in floats (144B, conflict-free)
#define ABYTES (BM * ASTR * 4) // 36864
#define BBYTES (BN * ASTR * 4) // 18432
#define BUFB   (ABYTES + BBYTES)   // 55296
#define SMEM_TOTAL (3 * BUFB)      // 165888

#define NCHUNKS_W (VOCAB * NCHUNK)     // 771072 k-chunks in W
#define WCVT_BLOCKS (NCHUNKS_W / 256)  // 3012 (exact)

// Scratch (static: no allocations allowed)
__device__ float g_Hn[(size_t)NTOK * D_MODEL];      // k-permuted, tf32-formatted
__device__ float g_Wt[(size_t)VOCAB * D_MODEL];     // k-permuted, tf32-formatted
__device__ float g_pmax[(size_t)NTOK * NTILES_N];
__device__ float g_psum[(size_t)NTOK * NTILES_N];
__device__ float g_nll[NTOK];
__device__ float g_cnt[NTOK];

__device__ __forceinline__ float f2tf32f(float x) {
    unsigned r;
    asm("cvt.rna.tf32.f32 %0, %1;" : "=r"(r) : "f"(x));
    return __uint_as_float(r);
}
__device__ __forceinline__ uint32_t smem_u32(const void* p) {
    return (uint32_t)__cvta_generic_to_shared(p);
}
__device__ __forceinline__ void cp16(uint32_t dst, const void* src) {
    asm volatile("cp.async.cg.shared.global [%0], [%1], 16;"
                 :: "r"(dst), "l"(src) : "memory");
}
#define CP_COMMIT() asm volatile("cp.async.commit_group;" ::: "memory")
#define CP_WAIT(n)  asm volatile("cp.async.wait_group %0;" :: "n"(n) : "memory")

// ---------------------------------------------------------------------------
// 1) Fused prep.
//    Permutation within each 32-float k-chunk: src k -> pos (k%4)*8 + k/4.
//    Inverse: pos p <- k = (p%8)*4 + p/8.
//    Blocks [0,NTOK): RMSNorm -> g_Hn (permuted, tf32).
//    Blocks [NTOK, NTOK+WCVT_BLOCKS): convert W -> g_Wt (permuted, tf32).
// ---------------------------------------------------------------------------
__global__ void prep_kernel(const float* __restrict__ x,
                            const float* __restrict__ w,
                            const float* __restrict__ W) {
    const int tid = threadIdx.x;
    if (blockIdx.x < NTOK) {
        const int row = blockIdx.x;
        const float* xr = x + (size_t)row * D_MODEL;
        float ssq = 0.f;
        #pragma unroll
        for (int i = 0; i < 3; ++i) { float v = xr[tid + i * 256]; ssq += v * v; }
        __shared__ float red[256];
        red[tid] = ssq; __syncthreads();
        #pragma unroll
        for (int s = 128; s > 0; s >>= 1) {
            if (tid < s) red[tid] += red[tid + s];
            __syncthreads();
        }
        const float inv = rsqrtf(red[0] * (1.0f / D_MODEL) + 1e-6f);
        #pragma unroll
        for (int i = 0; i < 3; ++i) {
            const int k = tid + i * 256;
            const int j = k & 31;
            const int pos = (k & ~31) + ((j & 3) << 3) + (j >> 2);
            g_Hn[(size_t)row * D_MODEL + pos] = f2tf32f(xr[k] * inv * w[k]);
        }
    } else {
        // one 32-float chunk per thread
        const size_t c = (size_t)(blockIdx.x - NTOK) * 256 + tid;
        const float* src = W + c * 32;
        float* dst = g_Wt + c * 32;
        float v[32];
        #pragma unroll
        for (int j = 0; j < 8; ++j)
            *(float4*)(v + j * 4) = *(const float4*)(src + j * 4);
        #pragma unroll
        for (int p4 = 0; p4 < 8; ++p4) {
            float4 o;
            o.x = f2tf32f(v[((p4 * 4 + 0) % 8) * 4 + (p4 * 4 + 0) / 8]);
            o.y = f2tf32f(v[((p4 * 4 + 1) % 8) * 4 + (p4 * 4 + 1) / 8]);
            o.z = f2tf32f(v[((p4 * 4 + 2) % 8) * 4 + (p4 * 4 + 2) / 8]);
            o.w = f2tf32f(v[((p4 * 4 + 3) % 8) * 4 + (p4 * 4 + 3) / 8]);
            *(float4*)(dst + p4 * 4) = o;
        }
    }
}

// ---------------------------------------------------------------------------
// 2) GEMM (mma.sync tf32) 256x128 tile, cp.async 3-stage, LDS.128 fragments,
//    fused row-wise logsumexp partials.
// ---------------------------------------------------------------------------
__device__ __forceinline__ void stage_chunk(uint32_t sbuf, int kt,
                                            size_t bm, size_t bn, int tid) {
    const int row = tid >> 3;
    const int c16 = tid & 7;
    #pragma unroll
    for (int i = 0; i < 8; ++i) {
        const int r = row + i * 32;
        cp16(sbuf + (uint32_t)(r * (ASTR * 4) + c16 * 16),
             g_Hn + (bm + r) * D_MODEL + kt * BKF + c16 * 4);
    }
    #pragma unroll
    for (int i = 0; i < 4; ++i) {
        const int r = row + i * 32;
        cp16(sbuf + ABYTES + (uint32_t)(r * (ASTR * 4) + c16 * 16),
             g_Wt + (bn + r) * D_MODEL + kt * BKF + c16 * 4);
    }
}

__global__ void __launch_bounds__(256)
gemm_kernel(float* __restrict__ C) {
    extern __shared__ float smem[];
    const uint32_t sb = smem_u32(smem);

    const int tid  = threadIdx.x;
    const int wid  = tid >> 5;
    const int lane = tid & 31;
    const int gid  = lane >> 2;
    const int tig  = lane & 3;

    const size_t bm = (size_t)blockIdx.y * BM;
    const size_t bn = (size_t)blockIdx.x * BN;

    float acc[2][16][4];
    #pragma unroll
    for (int mt = 0; mt < 2; ++mt)
        #pragma unroll
        for (int nt = 0; nt < 16; ++nt)
            #pragma unroll
            for (int k = 0; k < 4; ++k) acc[mt][nt][k] = 0.f;

    stage_chunk(sb, 0, bm, bn, tid); CP_COMMIT();
    stage_chunk(sb + BUFB, 1, bm, bn, tid); CP_COMMIT();

    const int rbase = wid * 32 + gid;
    for (int kt = 0; kt < NCHUNK; ++kt) {
        if (kt < NCHUNK - 1) { CP_WAIT(1); } else { CP_WAIT(0); }
        __syncthreads();

        if (kt + 2 < NCHUNK) {
            stage_chunk(sb + ((kt + 2) % 3) * BUFB, kt + 2, bm, bn, tid);
            CP_COMMIT();
        }

        const float* As = smem + ((kt % 3) * BUFB) / 4;
        const float* Bs = As + ABYTES / 4;

        // A fragments: rows r, r+8 per mt; LDS.128 pairs give all 4 k-steps.
        // layout per float4 at (row, tig*8):   (a0_ks0, a2_ks0, a0_ks1, a2_ks1)
        //                 at (row, tig*8+4):   (a0_ks2, a2_ks2, a0_ks3, a2_ks3)
        float4 aL[2][2], aH[2][2];
        #pragma unroll
        for (int mt = 0; mt < 2; ++mt) {
            const int r = rbase + mt * 16;
            aL[mt][0] = *(const float4*)(As + r * ASTR + tig * 8);
            aL[mt][1] = *(const float4*)(As + r * ASTR + tig * 8 + 4);
            aH[mt][0] = *(const float4*)(As + (r + 8) * ASTR + tig * 8);
            aH[mt][1] = *(const float4*)(As + (r + 8) * ASTR + tig * 8 + 4);
        }

        #pragma unroll
        for (int nt = 0; nt < 16; ++nt) {
            const int n = nt * 8 + gid;
            // (b0_ks0, b1_ks0, b0_ks1, b1_ks1), (b0_ks2, b1_ks2, b0_ks3, b1_ks3)
            const float4 b01 = *(const float4*)(Bs + n * ASTR + tig * 8);
            const float4 b23 = *(const float4*)(Bs + n * ASTR + tig * 8 + 4);
            const float bv[8] = { b01.x, b01.y, b01.z, b01.w,
                                  b23.x, b23.y, b23.z, b23.w };
            #pragma unroll
            for (int ks = 0; ks < 4; ++ks) {
                const float4& fl = (ks < 2) ? aL[0][0] : aL[0][1];  // placeholder
                (void)fl;
                #pragma unroll
                for (int mt = 0; mt < 2; ++mt) {
                    const float4 l = aL[mt][ks >> 1];
                    const float4 h = aH[mt][ks >> 1];
                    const float a0 = (ks & 1) ? l.z : l.x;
                    const float a2 = (ks & 1) ? l.w : l.y;
                    const float a1 = (ks & 1) ? h.z : h.x;
                    const float a3 = (ks & 1) ? h.w : h.y;
                    asm volatile(
                        "mma.sync.aligned.m16n8k8.row.col.f32.tf32.tf32.f32 "
                        "{%0,%1,%2,%3},{%4,%5,%6,%7},{%8,%9},{%0,%1,%2,%3};\n"
                        : "+f"(acc[mt][nt][0]), "+f"(acc[mt][nt][1]),
                          "+f"(acc[mt][nt][2]), "+f"(acc[mt][nt][3])
                        : "r"(__float_as_uint(a0)), "r"(__float_as_uint(a1)),
                          "r"(__float_as_uint(a2)), "r"(__float_as_uint(a3)),
                          "r"(__float_as_uint(bv[ks * 2])),
                          "r"(__float_as_uint(bv[ks * 2 + 1])));
                }
            }
        }
        // no bottom sync: next iteration's top sync separates reads of buf kt%3
        // from its restaging (which happens strictly after that sync).
    }

    // Epilogue: store C + fused per-row logsumexp partials over these 128 cols.
    #pragma unroll
    for (int mt = 0; mt < 2; ++mt) {
        #pragma unroll
        for (int h = 0; h < 2; ++h) {
            const size_t r = bm + wid * 32 + mt * 16 + gid + h * 8;
            float* cr = C + r * VOCAB + bn + tig * 2;
            float m = -1e30f;
            #pragma unroll
            for (int nt = 0; nt < 16; ++nt) {
                const float v0 = acc[mt][nt][2 * h];
                const float v1 = acc[mt][nt][2 * h + 1];
                cr[nt * 8]     = v0;
                cr[nt * 8 + 1] = v1;
                m = fmaxf(m, fmaxf(v0, v1));
            }
            float s = 0.f;
            #pragma unroll
            for (int nt = 0; nt < 16; ++nt) {
                s += __expf(acc[mt][nt][2 * h] - m);
                s += __expf(acc[mt][nt][2 * h + 1] - m);
            }
            #pragma unroll
            for (int d = 1; d < 4; d <<= 1) {
                const float om = __shfl_xor_sync(0xFFFFFFFFu, m, d);
                const float os = __shfl_xor_sync(0xFFFFFFFFu, s, d);
                const float nm = fmaxf(m, om);
                s = s * __expf(m - nm) + os * __expf(om - nm);
                m = nm;
            }
            if (tig == 0) {
                g_pmax[r * NTILES_N + blockIdx.x] = m;
                g_psum[r * NTILES_N + blockIdx.x] = s;
            }
        }
    }
}

// ---------------------------------------------------------------------------
// 3) Combine partials -> per-row NLL
// ---------------------------------------------------------------------------
__global__ void combine_loss_kernel(const float* __restrict__ scores,
                                    const int* __restrict__ labels) {
    const int row = blockIdx.x;
    const int tid = threadIdx.x;
    __shared__ float red[256];

    float pm = -1e30f;
    if (tid < NTILES_N) pm = g_pmax[(size_t)row * NTILES_N + tid];
    red[tid] = pm; __syncthreads();
    #pragma unroll
    for (int s = 128; s > 0; s >>= 1) {
        if (tid < s) red[tid] = fmaxf(red[tid], red[tid + s]);
        __syncthreads();
    }
    const float M = red[0];
    __syncthreads();

    float ps = 0.f;
    if (tid < NTILES_N)
        ps = g_psum[(size_t)row * NTILES_N + tid] * __expf(pm - M);
    red[tid] = ps; __syncthreads();
    #pragma unroll
    for (int s = 128; s > 0; s >>= 1) {
        if (tid < s) red[tid] += red[tid + s];
        __syncthreads();
    }

    if (tid == 0) {
        const int l = labels[row];
        if (l != -100) {
            const int sl = (l >= 0 && l < VOCAB) ? l : 0;
            g_nll[row] = logf(red[0]) + M - scores[(size_t)row * VOCAB + sl];
            g_cnt[row] = 1.f;
        } else {
            g_nll[row] = 0.f;
            g_cnt[row] = 0.f;
        }
    }
}

// ---------------------------------------------------------------------------
// 4) Deterministic final reduction
// ---------------------------------------------------------------------------
__global__ void finalize_kernel(float* __restrict__ loss_out) {
    if (loss_out == nullptr) return;
    __shared__ float rs[256], rc[256];
    const int tid = threadIdx.x;
    float s = 0.f, c = 0.f;
    for (int i = tid; i < NTOK; i += 256) { s += g_nll[i]; c += g_cnt[i]; }
    rs[tid] = s; rc[tid] = c; __syncthreads();
    #pragma unroll
    for (int st = 128; st > 0; st >>= 1) {
        if (tid < st) { rs[tid] += rs[tid + st]; rc[tid] += rc[tid + st]; }
        __syncthreads();
    }
    if (tid == 0) loss_out[0] = rs[0] / fmaxf(rc[0], 1.f);
}

// ---------------------------------------------------------------------------
extern "C" void kernel_launch(void* const* d_in, const int* in_sizes, int n_in,
                              void* d_out, int out_size) {
    const float* hidden = (const float*)d_in[0];
    const int*   labels = (const int*)d_in[1];
    const float* lnw    = (const float*)d_in[2];
    const float* W      = (const float*)d_in[3];

    float* out = (float*)d_out;
    long long extra = (long long)out_size - (long long)NTOK * (long long)VOCAB;
    if (extra < 0) extra = 0;
    float* scores   = out + extra;
    float* loss_ptr = (extra >= 1) ? out : nullptr;

    static int smem_set = 0;
    if (!smem_set) {
        cudaFuncSetAttribute(gemm_kernel,
                             cudaFuncAttributeMaxDynamicSharedMemorySize, SMEM_TOTAL);
        smem_set = 1;
    }

    prep_kernel<<<NTOK + WCVT_BLOCKS, 256>>>(hidden, lnw, W);
    gemm_kernel<<<dim3(NTILES_N, NTOK / BM), 256, SMEM_TOTAL>>>(scores);
    combine_loss_kernel<<<NTOK, 256>>>(scores, labels);
    finalize_kernel<<<1, 256>>>(loss_ptr);
}

// round 6
// speedup vs baseline: 1.0066x; 1.0066x over previous
#include <cuda_runtime.h>
#include <math.h>
#include <stdint.h>

#define D_MODEL 768
#define VOCAB   32128
#define NTOK    2048
#define NTILES_N 251           // VOCAB / 128
#define BM 256
#define BN 128
#define BKF 32                 // k-floats per chunk
#define NCHUNK (D_MODEL / BKF) // 24
#define ASTR 36                // smem row stride in floats (144B, conflict-free)
#define ABYTES (BM * ASTR * 4) // 36864
#define BBYTES (BN * ASTR * 4) // 18432
#define BUFB   (ABYTES + BBYTES)   // 55296
#define SMEM_TOTAL (3 * BUFB)      // 165888

#define NCHUNKS_W (VOCAB * NCHUNK)     // 771072 k-chunks in W
#define WCVT_BLOCKS (NCHUNKS_W / 256)  // 3012 (exact)

// Scratch (static: no allocations allowed)
__device__ float g_Hn[(size_t)NTOK * D_MODEL];      // k-permuted, tf32-formatted
__device__ float g_Wt[(size_t)VOCAB * D_MODEL];     // k-permuted, tf32-formatted
__device__ float g_pmax[(size_t)NTOK * NTILES_N];
__device__ float g_psum[(size_t)NTOK * NTILES_N];
__device__ float g_nll[NTOK];
__device__ float g_cnt[NTOK];

__device__ __forceinline__ float f2tf32f(float x) {
    unsigned r;
    asm("cvt.rna.tf32.f32 %0, %1;" : "=r"(r) : "f"(x));
    return __uint_as_float(r);
}
__device__ __forceinline__ uint32_t smem_u32(const void* p) {
    return (uint32_t)__cvta_generic_to_shared(p);
}
__device__ __forceinline__ void cp16(uint32_t dst, const void* src) {
    asm volatile("cp.async.cg.shared.global [%0], [%1], 16;"
                 :: "r"(dst), "l"(src) : "memory");
}
#define CP_COMMIT() asm volatile("cp.async.commit_group;" ::: "memory")
#define CP_WAIT(n)  asm volatile("cp.async.wait_group %0;" :: "n"(n) : "memory")

#define MMA_TF32(acc, A0, A1, A2, A3, B0, B1)                                  \
    asm volatile(                                                              \
        "mma.sync.aligned.m16n8k8.row.col.f32.tf32.tf32.f32 "                  \
        "{%0,%1,%2,%3},{%4,%5,%6,%7},{%8,%9},{%0,%1,%2,%3};\n"                 \
        : "+f"((acc)[0]), "+f"((acc)[1]), "+f"((acc)[2]), "+f"((acc)[3])       \
        : "r"(__float_as_uint(A0)), "r"(__float_as_uint(A1)),                  \
          "r"(__float_as_uint(A2)), "r"(__float_as_uint(A3)),                  \
          "r"(__float_as_uint(B0)), "r"(__float_as_uint(B1)))

// ---------------------------------------------------------------------------
// 1) Fused prep.
//    Permutation within each 32-float k-chunk: src k -> pos (k%4)*8 + k/4.
//    Blocks [0,NTOK): RMSNorm -> g_Hn (permuted, tf32).
//    Blocks [NTOK, NTOK+WCVT_BLOCKS): convert W -> g_Wt (permuted, tf32).
// ---------------------------------------------------------------------------
__global__ void prep_kernel(const float* __restrict__ x,
                            const float* __restrict__ w,
                            const float* __restrict__ W) {
    const int tid = threadIdx.x;
    if (blockIdx.x < NTOK) {
        const int row = blockIdx.x;
        const float* xr = x + (size_t)row * D_MODEL;
        float ssq = 0.f;
        #pragma unroll
        for (int i = 0; i < 3; ++i) { float v = xr[tid + i * 256]; ssq += v * v; }
        __shared__ float red[256];
        red[tid] = ssq; __syncthreads();
        #pragma unroll
        for (int s = 128; s > 0; s >>= 1) {
            if (tid < s) red[tid] += red[tid + s];
            __syncthreads();
        }
        const float inv = rsqrtf(red[0] * (1.0f / D_MODEL) + 1e-6f);
        #pragma unroll
        for (int i = 0; i < 3; ++i) {
            const int k = tid + i * 256;
            const int j = k & 31;
            const int pos = (k & ~31) + ((j & 3) << 3) + (j >> 2);
            g_Hn[(size_t)row * D_MODEL + pos] = f2tf32f(xr[k] * inv * w[k]);
        }
    } else {
        const size_t c = (size_t)(blockIdx.x - NTOK) * 256 + tid;
        const float* src = W + c * 32;
        float* dst = g_Wt + c * 32;
        float v[32];
        #pragma unroll
        for (int j = 0; j < 8; ++j)
            *(float4*)(v + j * 4) = *(const float4*)(src + j * 4);
        #pragma unroll
        for (int p4 = 0; p4 < 8; ++p4) {
            float4 o;
            o.x = f2tf32f(v[((p4 * 4 + 0) % 8) * 4 + (p4 * 4 + 0) / 8]);
            o.y = f2tf32f(v[((p4 * 4 + 1) % 8) * 4 + (p4 * 4 + 1) / 8]);
            o.z = f2tf32f(v[((p4 * 4 + 2) % 8) * 4 + (p4 * 4 + 2) / 8]);
            o.w = f2tf32f(v[((p4 * 4 + 3) % 8) * 4 + (p4 * 4 + 3) / 8]);
            *(float4*)(dst + p4 * 4) = o;
        }
    }
}

// ---------------------------------------------------------------------------
// 2) GEMM (mma.sync tf32) 256x128 tile, cp.async 3-stage, LDS.128 fragments,
//    ks-pair ordering (same-acc distance = 16 MMAs), fused lse partials.
// ---------------------------------------------------------------------------
__device__ __forceinline__ void stage_chunk(uint32_t sbuf, int kt,
                                            size_t bm, size_t bn, int tid) {
    const int row = tid >> 3;
    const int c16 = tid & 7;
    #pragma unroll
    for (int i = 0; i < 8; ++i) {
        const int r = row + i * 32;
        cp16(sbuf + (uint32_t)(r * (ASTR * 4) + c16 * 16),
             g_Hn + (bm + r) * D_MODEL + kt * BKF + c16 * 4);
    }
    #pragma unroll
    for (int i = 0; i < 4; ++i) {
        const int r = row + i * 32;
        cp16(sbuf + ABYTES + (uint32_t)(r * (ASTR * 4) + c16 * 16),
             g_Wt + (bn + r) * D_MODEL + kt * BKF + c16 * 4);
    }
}

__global__ void __launch_bounds__(256)
gemm_kernel(float* __restrict__ C) {
    extern __shared__ float smem[];
    const uint32_t sb = smem_u32(smem);

    const int tid  = threadIdx.x;
    const int wid  = tid >> 5;
    const int lane = tid & 31;
    const int gid  = lane >> 2;
    const int tig  = lane & 3;

    const size_t bm = (size_t)blockIdx.y * BM;
    const size_t bn = (size_t)blockIdx.x * BN;

    float acc[2][16][4];
    #pragma unroll
    for (int mt = 0; mt < 2; ++mt)
        #pragma unroll
        for (int nt = 0; nt < 16; ++nt)
            #pragma unroll
            for (int k = 0; k < 4; ++k) acc[mt][nt][k] = 0.f;

    stage_chunk(sb, 0, bm, bn, tid); CP_COMMIT();
    stage_chunk(sb + BUFB, 1, bm, bn, tid); CP_COMMIT();

    const int rbase = wid * 32 + gid;
    for (int kt = 0; kt < NCHUNK; ++kt) {
        if (kt < NCHUNK - 1) { CP_WAIT(1); } else { CP_WAIT(0); }
        __syncthreads();

        if (kt + 2 < NCHUNK) {
            stage_chunk(sb + ((kt + 2) % 3) * BUFB, kt + 2, bm, bn, tid);
            CP_COMMIT();
        }

        const float* As = smem + ((kt % 3) * BUFB) / 4;
        const float* Bs = As + ABYTES / 4;

        // Permuted layout: float4 at col tig*8 + kp*4 holds, for the two
        // k-steps ks = 2*kp, 2*kp+1:   (v_k@ks0, v_k+4@ks0, v_k@ks1, v_k+4@ks1)
        #pragma unroll
        for (int kp = 0; kp < 2; ++kp) {
            float4 la[2], ha[2];
            #pragma unroll
            for (int mt = 0; mt < 2; ++mt) {
                const int r = rbase + mt * 16;
                la[mt] = *(const float4*)(As + r * ASTR + tig * 8 + kp * 4);
                ha[mt] = *(const float4*)(As + (r + 8) * ASTR + tig * 8 + kp * 4);
            }
            #pragma unroll
            for (int nh = 0; nh < 2; ++nh) {
                float4 bf[8];
                #pragma unroll
                for (int j = 0; j < 8; ++j) {
                    const int n = (nh * 8 + j) * 8 + gid;
                    bf[j] = *(const float4*)(Bs + n * ASTR + tig * 8 + kp * 4);
                }
                // ks even (x,y components): all 16 MMAs, then ks odd (z,w).
                #pragma unroll
                for (int j = 0; j < 8; ++j)
                    #pragma unroll
                    for (int mt = 0; mt < 2; ++mt)
                        MMA_TF32(acc[mt][nh * 8 + j],
                                 la[mt].x, ha[mt].x, la[mt].y, ha[mt].y,
                                 bf[j].x, bf[j].y);
                #pragma unroll
                for (int j = 0; j < 8; ++j)
                    #pragma unroll
                    for (int mt = 0; mt < 2; ++mt)
                        MMA_TF32(acc[mt][nh * 8 + j],
                                 la[mt].z, ha[mt].z, la[mt].w, ha[mt].w,
                                 bf[j].z, bf[j].w);
            }
        }
        // no bottom sync: next iteration's top sync separates reads of buf kt%3
        // from its restaging.
    }

    // Epilogue: store C + fused per-row logsumexp partials over these 128 cols.
    #pragma unroll
    for (int mt = 0; mt < 2; ++mt) {
        #pragma unroll
        for (int h = 0; h < 2; ++h) {
            const size_t r = bm + wid * 32 + mt * 16 + gid + h * 8;
            float* cr = C + r * VOCAB + bn + tig * 2;
            float m = -1e30f;
            #pragma unroll
            for (int nt = 0; nt < 16; ++nt) {
                const float v0 = acc[mt][nt][2 * h];
                const float v1 = acc[mt][nt][2 * h + 1];
                cr[nt * 8]     = v0;
                cr[nt * 8 + 1] = v1;
                m = fmaxf(m, fmaxf(v0, v1));
            }
            float s = 0.f;
            #pragma unroll
            for (int nt = 0; nt < 16; ++nt) {
                s += __expf(acc[mt][nt][2 * h] - m);
                s += __expf(acc[mt][nt][2 * h + 1] - m);
            }
            #pragma unroll
            for (int d = 1; d < 4; d <<= 1) {
                const float om = __shfl_xor_sync(0xFFFFFFFFu, m, d);
                const float os = __shfl_xor_sync(0xFFFFFFFFu, s, d);
                const float nm = fmaxf(m, om);
                s = s * __expf(m - nm) + os * __expf(om - nm);
                m = nm;
            }
            if (tig == 0) {
                g_pmax[r * NTILES_N + blockIdx.x] = m;
                g_psum[r * NTILES_N + blockIdx.x] = s;
            }
        }
    }
}

// ---------------------------------------------------------------------------
// 3) Combine partials -> per-row NLL
// ---------------------------------------------------------------------------
__global__ void combine_loss_kernel(const float* __restrict__ scores,
                                    const int* __restrict__ labels) {
    const int row = blockIdx.x;
    const int tid = threadIdx.x;
    __shared__ float red[256];

    float pm = -1e30f;
    if (tid < NTILES_N) pm = g_pmax[(size_t)row * NTILES_N + tid];
    red[tid] = pm; __syncthreads();
    #pragma unroll
    for (int s = 128; s > 0; s >>= 1) {
        if (tid < s) red[tid] = fmaxf(red[tid], red[tid + s]);
        __syncthreads();
    }
    const float M = red[0];
    __syncthreads();

    float ps = 0.f;
    if (tid < NTILES_N)
        ps = g_psum[(size_t)row * NTILES_N + tid] * __expf(pm - M);
    red[tid] = ps; __syncthreads();
    #pragma unroll
    for (int s = 128; s > 0; s >>= 1) {
        if (tid < s) red[tid] += red[tid + s];
        __syncthreads();
    }

    if (tid == 0) {
        const int l = labels[row];
        if (l != -100) {
            const int sl = (l >= 0 && l < VOCAB) ? l : 0;
            g_nll[row] = logf(red[0]) + M - scores[(size_t)row * VOCAB + sl];
            g_cnt[row] = 1.f;
        } else {
            g_nll[row] = 0.f;
            g_cnt[row] = 0.f;
        }
    }
}

// ---------------------------------------------------------------------------
// 4) Deterministic final reduction
// ---------------------------------------------------------------------------
__global__ void finalize_kernel(float* __restrict__ loss_out) {
    if (loss_out == nullptr) return;
    __shared__ float rs[256], rc[256];
    const int tid = threadIdx.x;
    float s = 0.f, c = 0.f;
    for (int i = tid; i < NTOK; i += 256) { s += g_nll[i]; c += g_cnt[i]; }
    rs[tid] = s; rc[tid] = c; __syncthreads();
    #pragma unroll
    for (int st = 128; st > 0; st >>= 1) {
        if (tid < st) { rs[tid] += rs[tid + st]; rc[tid] += rc[tid + st]; }
        __syncthreads();
    }
    if (tid == 0) loss_out[0] = rs[0] / fmaxf(rc[0], 1.f);
}

// ---------------------------------------------------------------------------
extern "C" void kernel_launch(void* const* d_in, const int* in_sizes, int n_in,
                              void* d_out, int out_size) {
    const float* hidden = (const float*)d_in[0];
    const int*   labels = (const int*)d_in[1];
    const float* lnw    = (const float*)d_in[2];
    const float* W      = (const float*)d_in[3];

    float* out = (float*)d_out;
    long long extra = (long long)out_size - (long long)NTOK * (long long)VOCAB;
    if (extra < 0) extra = 0;
    float* scores   = out + extra;
    float* loss_ptr = (extra >= 1) ? out : nullptr;

    static int smem_set = 0;
    if (!smem_set) {
        cudaFuncSetAttribute(gemm_kernel,
                             cudaFuncAttributeMaxDynamicSharedMemorySize, SMEM_TOTAL);
        smem_set = 1;
    }

    prep_kernel<<<NTOK + WCVT_BLOCKS, 256>>>(hidden, lnw, W);
    gemm_kernel<<<dim3(NTILES_N, NTOK / BM), 256, SMEM_TOTAL>>>(scores);
    combine_loss_kernel<<<NTOK, 256>>>(scores, labels);
    finalize_kernel<<<1, 256>>>(loss_ptr);
}

// round 7
// speedup vs baseline: 2.0240x; 2.0107x over previous
#include <cuda_runtime.h>
#include <cuda_fp16.h>
#include <math.h>
#include <stdint.h>

#define D_MODEL 768
#define VOCAB   32128
#define NTOK    2048
#define NTILES_N 251           // VOCAB / 128
#define BM 256
#define BN 128
#define BKH 64                 // k-halfs per chunk (128 B per row)
#define NCHUNK (D_MODEL / BKH) // 12
#define ASTRH 72               // smem row stride in halfs (144 B, conflict-free)
#define ABYTES (BM * ASTRH * 2)    // 36864
#define BBYTES (BN * ASTRH * 2)    // 18432
#define BUFB   (ABYTES + BBYTES)   // 55296
#define SMEM_TOTAL (3 * BUFB)      // 165888

#define WCVT_BLOCKS 6024       // (32128*768/4) float4s / (256*4) = exact

// Scratch (static: no allocations allowed)
__device__ __half g_Hh[(size_t)NTOK * D_MODEL];
__device__ __half g_Wh[(size_t)VOCAB * D_MODEL];
__device__ float  g_pmax[(size_t)NTOK * NTILES_N];
__device__ float  g_psum[(size_t)NTOK * NTILES_N];
__device__ float  g_nll[NTOK];
__device__ float  g_cnt[NTOK];

__device__ __forceinline__ uint32_t smem_u32(const void* p) {
    return (uint32_t)__cvta_generic_to_shared(p);
}
__device__ __forceinline__ void cp16(uint32_t dst, const void* src) {
    asm volatile("cp.async.cg.shared.global [%0], [%1], 16;"
                 :: "r"(dst), "l"(src) : "memory");
}
#define CP_COMMIT() asm volatile("cp.async.commit_group;" ::: "memory")
#define CP_WAIT(n)  asm volatile("cp.async.wait_group %0;" :: "n"(n) : "memory")

#define MMA_F16(acc, A0, A1, A2, A3, B0, B1)                                   \
    asm volatile(                                                              \
        "mma.sync.aligned.m16n8k16.row.col.f32.f16.f16.f32 "                   \
        "{%0,%1,%2,%3},{%4,%5,%6,%7},{%8,%9},{%0,%1,%2,%3};\n"                 \
        : "+f"((acc)[0]), "+f"((acc)[1]), "+f"((acc)[2]), "+f"((acc)[3])       \
        : "r"(A0), "r"(A1), "r"(A2), "r"(A3), "r"(B0), "r"(B1))

// ---------------------------------------------------------------------------
// 1) Fused prep (all coalesced).
//    Blocks [0,NTOK): RMSNorm -> g_Hh (fp16).
//    Blocks [NTOK, NTOK+WCVT_BLOCKS): W -> g_Wh (fp16), strided float4 reads.
// ---------------------------------------------------------------------------
__global__ void prep_kernel(const float* __restrict__ x,
                            const float* __restrict__ w,
                            const float* __restrict__ W) {
    const int tid = threadIdx.x;
    if (blockIdx.x < NTOK) {
        const int row = blockIdx.x;
        const float* xr = x + (size_t)row * D_MODEL;
        float ssq = 0.f;
        #pragma unroll
        for (int i = 0; i < 3; ++i) { float v = xr[tid + i * 256]; ssq += v * v; }
        __shared__ float red[256];
        red[tid] = ssq; __syncthreads();
        #pragma unroll
        for (int s = 128; s > 0; s >>= 1) {
            if (tid < s) red[tid] += red[tid + s];
            __syncthreads();
        }
        const float inv = rsqrtf(red[0] * (1.0f / D_MODEL) + 1e-6f);
        #pragma unroll
        for (int i = 0; i < 3; ++i) {
            const int k = tid + i * 256;
            g_Hh[(size_t)row * D_MODEL + k] = __float2half_rn(xr[k] * inv * w[k]);
        }
    } else {
        const size_t nf4 = (size_t)VOCAB * D_MODEL / 4;       // 6168576
        const float4* src = (const float4*)W;
        const size_t t0 = (size_t)(blockIdx.x - NTOK) * 256 + tid;
        #pragma unroll
        for (int i = 0; i < 4; ++i) {
            const size_t idx = t0 + (size_t)i * WCVT_BLOCKS * 256;
            if (idx < nf4) {
                const float4 v = src[idx];
                __half2* d = (__half2*)(g_Wh + idx * 4);
                d[0] = __floats2half2_rn(v.x, v.y);
                d[1] = __floats2half2_rn(v.z, v.w);
            }
        }
    }
}

// ---------------------------------------------------------------------------
// 2) GEMM (mma.sync f16 m16n8k16) 256x128 tile, cp.async 3-stage,
//    fused row-wise logsumexp partials.
// ---------------------------------------------------------------------------
__device__ __forceinline__ void stage_chunk(uint32_t sbuf, int kt,
                                            size_t bm, size_t bn, int tid) {
    const int row = tid >> 3;          // 0..31
    const int c16 = tid & 7;           // 16B unit within 128B row
    #pragma unroll
    for (int i = 0; i < 8; ++i) {      // A: 256 rows
        const int r = row + i * 32;
        cp16(sbuf + (uint32_t)(r * (ASTRH * 2) + c16 * 16),
             g_Hh + (bm + r) * D_MODEL + kt * BKH + c16 * 8);
    }
    #pragma unroll
    for (int i = 0; i < 4; ++i) {      // B: 128 rows
        const int r = row + i * 32;
        cp16(sbuf + ABYTES + (uint32_t)(r * (ASTRH * 2) + c16 * 16),
             g_Wh + (bn + r) * D_MODEL + kt * BKH + c16 * 8);
    }
}

__device__ __forceinline__ uint32_t lds_h2(const __half* p) {
    return *(const uint32_t*)p;
}

__global__ void __launch_bounds__(256)
gemm_kernel(float* __restrict__ C) {
    extern __shared__ __half smem[];
    const uint32_t sb = smem_u32(smem);

    const int tid  = threadIdx.x;
    const int wid  = tid >> 5;
    const int lane = tid & 31;
    const int gid  = lane >> 2;
    const int tig  = lane & 3;

    const size_t bm = (size_t)blockIdx.y * BM;
    const size_t bn = (size_t)blockIdx.x * BN;

    float acc[2][16][4];
    #pragma unroll
    for (int mt = 0; mt < 2; ++mt)
        #pragma unroll
        for (int nt = 0; nt < 16; ++nt)
            #pragma unroll
            for (int k = 0; k < 4; ++k) acc[mt][nt][k] = 0.f;

    stage_chunk(sb, 0, bm, bn, tid); CP_COMMIT();
    stage_chunk(sb + BUFB, 1, bm, bn, tid); CP_COMMIT();

    const int rbase = wid * 32 + gid;
    for (int kt = 0; kt < NCHUNK; ++kt) {
        if (kt < NCHUNK - 1) { CP_WAIT(1); } else { CP_WAIT(0); }
        __syncthreads();

        if (kt + 2 < NCHUNK) {
            stage_chunk(sb + ((kt + 2) % 3) * BUFB, kt + 2, bm, bn, tid);
            CP_COMMIT();
        }

        const __half* As = smem + ((size_t)(kt % 3) * BUFB) / 2;
        const __half* Bs = As + ABYTES / 2;

        #pragma unroll
        for (int ks = 0; ks < 4; ++ks) {          // 4 k16-steps per 64-k chunk
            const int kc = ks * 16 + tig * 2;     // half index within row
            uint32_t a[2][4];
            #pragma unroll
            for (int mt = 0; mt < 2; ++mt) {
                const int r = rbase + mt * 16;
                a[mt][0] = lds_h2(As + r * ASTRH + kc);
                a[mt][1] = lds_h2(As + (r + 8) * ASTRH + kc);
                a[mt][2] = lds_h2(As + r * ASTRH + kc + 8);
                a[mt][3] = lds_h2(As + (r + 8) * ASTRH + kc + 8);
            }
            #pragma unroll
            for (int nt = 0; nt < 16; ++nt) {
                const int n = nt * 8 + gid;
                const uint32_t b0 = lds_h2(Bs + n * ASTRH + kc);
                const uint32_t b1 = lds_h2(Bs + n * ASTRH + kc + 8);
                #pragma unroll
                for (int mt = 0; mt < 2; ++mt)
                    MMA_F16(acc[mt][nt], a[mt][0], a[mt][1], a[mt][2], a[mt][3],
                            b0, b1);
            }
        }
        // no bottom sync: next top sync orders reads before restaging.
    }

    // Epilogue: store C + fused per-row logsumexp partials over these 128 cols.
    #pragma unroll
    for (int mt = 0; mt < 2; ++mt) {
        #pragma unroll
        for (int h = 0; h < 2; ++h) {
            const size_t r = bm + wid * 32 + mt * 16 + gid + h * 8;
            float* cr = C + r * VOCAB + bn + tig * 2;
            float m = -1e30f;
            #pragma unroll
            for (int nt = 0; nt < 16; ++nt) {
                const float v0 = acc[mt][nt][2 * h];
                const float v1 = acc[mt][nt][2 * h + 1];
                cr[nt * 8]     = v0;
                cr[nt * 8 + 1] = v1;
                m = fmaxf(m, fmaxf(v0, v1));
            }
            float s = 0.f;
            #pragma unroll
            for (int nt = 0; nt < 16; ++nt) {
                s += __expf(acc[mt][nt][2 * h] - m);
                s += __expf(acc[mt][nt][2 * h + 1] - m);
            }
            #pragma unroll
            for (int d = 1; d < 4; d <<= 1) {
                const float om = __shfl_xor_sync(0xFFFFFFFFu, m, d);
                const float os = __shfl_xor_sync(0xFFFFFFFFu, s, d);
                const float nm = fmaxf(m, om);
                s = s * __expf(m - nm) + os * __expf(om - nm);
                m = nm;
            }
            if (tig == 0) {
                g_pmax[r * NTILES_N + blockIdx.x] = m;
                g_psum[r * NTILES_N + blockIdx.x] = s;
            }
        }
    }
}

// ---------------------------------------------------------------------------
// 3) Combine partials -> per-row NLL
// ---------------------------------------------------------------------------
__global__ void combine_loss_kernel(const float* __restrict__ scores,
                                    const int* __restrict__ labels) {
    const int row = blockIdx.x;
    const int tid = threadIdx.x;
    __shared__ float red[256];

    float pm = -1e30f;
    if (tid < NTILES_N) pm = g_pmax[(size_t)row * NTILES_N + tid];
    red[tid] = pm; __syncthreads();
    #pragma unroll
    for (int s = 128; s > 0; s >>= 1) {
        if (tid < s) red[tid] = fmaxf(red[tid], red[tid + s]);
        __syncthreads();
    }
    const float M = red[0];
    __syncthreads();

    float ps = 0.f;
    if (tid < NTILES_N)
        ps = g_psum[(size_t)row * NTILES_N + tid] * __expf(pm - M);
    red[tid] = ps; __syncthreads();
    #pragma unroll
    for (int s = 128; s > 0; s >>= 1) {
        if (tid < s) red[tid] += red[tid + s];
        __syncthreads();
    }

    if (tid == 0) {
        const int l = labels[row];
        if (l != -100) {
            const int sl = (l >= 0 && l < VOCAB) ? l : 0;
            g_nll[row] = logf(red[0]) + M - scores[(size_t)row * VOCAB + sl];
            g_cnt[row] = 1.f;
        } else {
            g_nll[row] = 0.f;
            g_cnt[row] = 0.f;
        }
    }
}

// ---------------------------------------------------------------------------
// 4) Deterministic final reduction
// ---------------------------------------------------------------------------
__global__ void finalize_kernel(float* __restrict__ loss_out) {
    if (loss_out == nullptr) return;
    __shared__ float rs[256], rc[256];
    const int tid = threadIdx.x;
    float s = 0.f, c = 0.f;
    for (int i = tid; i < NTOK; i += 256) { s += g_nll[i]; c += g_cnt[i]; }
    rs[tid] = s; rc[tid] = c; __syncthreads();
    #pragma unroll
    for (int st = 128; st > 0; st >>= 1) {
        if (tid < st) { rs[tid] += rs[tid + st]; rc[tid] += rc[tid + st]; }
        __syncthreads();
    }
    if (tid == 0) loss_out[0] = rs[0] / fmaxf(rc[0], 1.f);
}

// ---------------------------------------------------------------------------
extern "C" void kernel_launch(void* const* d_in, const int* in_sizes, int n_in,
                              void* d_out, int out_size) {
    const float* hidden = (const float*)d_in[0];
    const int*   labels = (const int*)d_in[1];
    const float* lnw    = (const float*)d_in[2];
    const float* W      = (const float*)d_in[3];

    float* out = (float*)d_out;
    long long extra = (long long)out_size - (long long)NTOK * (long long)VOCAB;
    if (extra < 0) extra = 0;
    float* scores   = out + extra;
    float* loss_ptr = (extra >= 1) ? out : nullptr;

    static int smem_set = 0;
    if (!smem_set) {
        cudaFuncSetAttribute(gemm_kernel,
                             cudaFuncAttributeMaxDynamicSharedMemorySize, SMEM_TOTAL);
        smem_set = 1;
    }

    prep_kernel<<<NTOK + WCVT_BLOCKS, 256>>>(hidden, lnw, W);
    gemm_kernel<<<dim3(NTILES_N, NTOK / BM), 256, SMEM_TOTAL>>>(scores);
    combine_loss_kernel<<<NTOK, 256>>>(scores, labels);
    finalize_kernel<<<1, 256>>>(loss_ptr);
}

// round 8
// speedup vs baseline: 2.1347x; 1.0547x over previous
#include <cuda_runtime.h>
#include <cuda_fp16.h>
#include <math.h>
#include <stdint.h>

#define D_MODEL 768
#define VOCAB   32128
#define NTOK    2048
#define NTILES_N 251           // VOCAB / 128
#define BM 256
#define BN 128
#define BKH 64                 // k-halfs per chunk (128 B per row)
#define NCHUNK (D_MODEL / BKH) // 12
#define ASTRH 72               // smem row stride in halfs (144 B, conflict-free)
#define ABYTES (BM * ASTRH * 2)    // 36864
#define BBYTES (BN * ASTRH * 2)    // 18432
#define BUFB   (ABYTES + BBYTES)   // 55296
#define SMEM_TOTAL (3 * BUFB)      // 165888  (>= epilogue S: 256*132*4=135168)
#define ESTR 132               // epilogue smem row stride in floats

#define WCVT_BLOCKS 6024       // (32128*768/4) float4s / (256*4) = exact

// Scratch (static: no allocations allowed)
__device__ __half g_Hh[(size_t)NTOK * D_MODEL];
__device__ __half g_Wh[(size_t)VOCAB * D_MODEL];
__device__ float  g_pmax[(size_t)NTOK * NTILES_N];
__device__ float  g_psum[(size_t)NTOK * NTILES_N];
__device__ float  g_nll[NTOK];
__device__ float  g_cnt[NTOK];
__device__ unsigned int g_done;   // zero-init; self-resetting per launch

__device__ __forceinline__ uint32_t smem_u32(const void* p) {
    return (uint32_t)__cvta_generic_to_shared(p);
}
__device__ __forceinline__ void cp16(uint32_t dst, const void* src) {
    asm volatile("cp.async.cg.shared.global [%0], [%1], 16;"
                 :: "r"(dst), "l"(src) : "memory");
}
#define CP_COMMIT() asm volatile("cp.async.commit_group;" ::: "memory")
#define CP_WAIT(n)  asm volatile("cp.async.wait_group %0;" :: "n"(n) : "memory")

#define MMA_F16(acc, A0, A1, A2, A3, B0, B1)                                   \
    asm volatile(                                                              \
        "mma.sync.aligned.m16n8k16.row.col.f32.f16.f16.f32 "                   \
        "{%0,%1,%2,%3},{%4,%5,%6,%7},{%8,%9},{%0,%1,%2,%3};\n"                 \
        : "+f"((acc)[0]), "+f"((acc)[1]), "+f"((acc)[2]), "+f"((acc)[3])       \
        : "r"(A0), "r"(A1), "r"(A2), "r"(A3), "r"(B0), "r"(B1))

// ---------------------------------------------------------------------------
// 1) Fused prep (all coalesced).
// ---------------------------------------------------------------------------
__global__ void prep_kernel(const float* __restrict__ x,
                            const float* __restrict__ w,
                            const float* __restrict__ W) {
    const int tid = threadIdx.x;
    if (blockIdx.x < NTOK) {
        const int row = blockIdx.x;
        const float* xr = x + (size_t)row * D_MODEL;
        float ssq = 0.f;
        #pragma unroll
        for (int i = 0; i < 3; ++i) { float v = xr[tid + i * 256]; ssq += v * v; }
        __shared__ float red[256];
        red[tid] = ssq; __syncthreads();
        #pragma unroll
        for (int s = 128; s > 0; s >>= 1) {
            if (tid < s) red[tid] += red[tid + s];
            __syncthreads();
        }
        const float inv = rsqrtf(red[0] * (1.0f / D_MODEL) + 1e-6f);
        #pragma unroll
        for (int i = 0; i < 3; ++i) {
            const int k = tid + i * 256;
            g_Hh[(size_t)row * D_MODEL + k] = __float2half_rn(xr[k] * inv * w[k]);
        }
    } else {
        const size_t nf4 = (size_t)VOCAB * D_MODEL / 4;       // 6168576
        const float4* src = (const float4*)W;
        const size_t t0 = (size_t)(blockIdx.x - NTOK) * 256 + tid;
        #pragma unroll
        for (int i = 0; i < 4; ++i) {
            const size_t idx = t0 + (size_t)i * WCVT_BLOCKS * 256;
            if (idx < nf4) {
                const float4 v = src[idx];
                __half2* d = (__half2*)(g_Wh + idx * 4);
                d[0] = __floats2half2_rn(v.x, v.y);
                d[1] = __floats2half2_rn(v.z, v.w);
            }
        }
    }
}

// ---------------------------------------------------------------------------
// 2) GEMM (mma.sync f16 m16n8k16) 256x128 tile, cp.async 3-stage,
//    smem-transposed coalesced epilogue + fused lse partials.
// ---------------------------------------------------------------------------
__device__ __forceinline__ void stage_chunk(uint32_t sbuf, int kt,
                                            size_t bm, size_t bn, int tid) {
    const int row = tid >> 3;
    const int c16 = tid & 7;
    #pragma unroll
    for (int i = 0; i < 8; ++i) {
        const int r = row + i * 32;
        cp16(sbuf + (uint32_t)(r * (ASTRH * 2) + c16 * 16),
             g_Hh + (bm + r) * D_MODEL + kt * BKH + c16 * 8);
    }
    #pragma unroll
    for (int i = 0; i < 4; ++i) {
        const int r = row + i * 32;
        cp16(sbuf + ABYTES + (uint32_t)(r * (ASTRH * 2) + c16 * 16),
             g_Wh + (bn + r) * D_MODEL + kt * BKH + c16 * 8);
    }
}

__device__ __forceinline__ uint32_t lds_h2(const __half* p) {
    return *(const uint32_t*)p;
}

__global__ void __launch_bounds__(256)
gemm_kernel(float* __restrict__ C) {
    extern __shared__ __half smem[];
    const uint32_t sb = smem_u32(smem);

    const int tid  = threadIdx.x;
    const int wid  = tid >> 5;
    const int lane = tid & 31;
    const int gid  = lane >> 2;
    const int tig  = lane & 3;

    const size_t bm = (size_t)blockIdx.y * BM;
    const size_t bn = (size_t)blockIdx.x * BN;

    float acc[2][16][4];
    #pragma unroll
    for (int mt = 0; mt < 2; ++mt)
        #pragma unroll
        for (int nt = 0; nt < 16; ++nt)
            #pragma unroll
            for (int k = 0; k < 4; ++k) acc[mt][nt][k] = 0.f;

    stage_chunk(sb, 0, bm, bn, tid); CP_COMMIT();
    stage_chunk(sb + BUFB, 1, bm, bn, tid); CP_COMMIT();

    const int rbase = wid * 32 + gid;
    for (int kt = 0; kt < NCHUNK; ++kt) {
        if (kt < NCHUNK - 1) { CP_WAIT(1); } else { CP_WAIT(0); }
        __syncthreads();

        if (kt + 2 < NCHUNK) {
            stage_chunk(sb + ((kt + 2) % 3) * BUFB, kt + 2, bm, bn, tid);
            CP_COMMIT();
        }

        const __half* As = smem + ((size_t)(kt % 3) * BUFB) / 2;
        const __half* Bs = As + ABYTES / 2;

        #pragma unroll
        for (int ks = 0; ks < 4; ++ks) {
            const int kc = ks * 16 + tig * 2;
            uint32_t a[2][4];
            #pragma unroll
            for (int mt = 0; mt < 2; ++mt) {
                const int r = rbase + mt * 16;
                a[mt][0] = lds_h2(As + r * ASTRH + kc);
                a[mt][1] = lds_h2(As + (r + 8) * ASTRH + kc);
                a[mt][2] = lds_h2(As + r * ASTRH + kc + 8);
                a[mt][3] = lds_h2(As + (r + 8) * ASTRH + kc + 8);
            }
            #pragma unroll
            for (int nt = 0; nt < 16; ++nt) {
                const int n = nt * 8 + gid;
                const uint32_t b0 = lds_h2(Bs + n * ASTRH + kc);
                const uint32_t b1 = lds_h2(Bs + n * ASTRH + kc + 8);
                #pragma unroll
                for (int mt = 0; mt < 2; ++mt)
                    MMA_F16(acc[mt][nt], a[mt][0], a[mt][1], a[mt][2], a[mt][3],
                            b0, b1);
            }
        }
    }

    // ---- Epilogue: accs -> smem (conflict-free), lse per row, coalesced STG.
    __syncthreads();                         // all warps done reading tiles
    float* S = (float*)smem;                 // [256][ESTR]
    #pragma unroll
    for (int mt = 0; mt < 2; ++mt)
        #pragma unroll
        for (int h = 0; h < 2; ++h) {
            const int rl = wid * 32 + mt * 16 + h * 8 + gid;
            #pragma unroll
            for (int nt = 0; nt < 16; ++nt)
                *(float2*)(S + rl * ESTR + nt * 8 + tig * 2) =
                    make_float2(acc[mt][nt][2 * h], acc[mt][nt][2 * h + 1]);
        }
    __syncthreads();

    // Per-row logsumexp partial: thread tid owns row tid.
    {
        const float* row = S + tid * ESTR;
        float m = -1e30f;
        #pragma unroll
        for (int c = 0; c < 128; c += 4) {
            const float4 v = *(const float4*)(row + c);
            m = fmaxf(m, fmaxf(fmaxf(v.x, v.y), fmaxf(v.z, v.w)));
        }
        float s = 0.f;
        #pragma unroll
        for (int c = 0; c < 128; c += 4) {
            const float4 v = *(const float4*)(row + c);
            s += __expf(v.x - m) + __expf(v.y - m)
               + __expf(v.z - m) + __expf(v.w - m);
        }
        g_pmax[(bm + tid) * NTILES_N + blockIdx.x] = m;
        g_psum[(bm + tid) * NTILES_N + blockIdx.x] = s;
    }

    // Coalesced C store: warp covers 32 consecutive cols of one row per instr.
    {
        const int col = tid & 127;
        const int rh  = tid >> 7;            // 0 or 1
        #pragma unroll 8
        for (int it = 0; it < 128; ++it) {
            const int rl = it * 2 + rh;
            C[(bm + rl) * (size_t)VOCAB + bn + col] = S[rl * ESTR + col];
        }
    }
}

// ---------------------------------------------------------------------------
// 3) Combine partials -> per-row NLL, fused deterministic final reduction
// ---------------------------------------------------------------------------
__global__ void combine_loss_kernel(const float* __restrict__ scores,
                                    const int* __restrict__ labels,
                                    float* __restrict__ loss_out) {
    const int row = blockIdx.x;
    const int tid = threadIdx.x;
    __shared__ float red[256];
    __shared__ float red2[256];
    __shared__ unsigned last;

    float pm = -1e30f;
    if (tid < NTILES_N) pm = g_pmax[(size_t)row * NTILES_N + tid];
    red[tid] = pm; __syncthreads();
    #pragma unroll
    for (int s = 128; s > 0; s >>= 1) {
        if (tid < s) red[tid] = fmaxf(red[tid], red[tid + s]);
        __syncthreads();
    }
    const float M = red[0];
    __syncthreads();

    float ps = 0.f;
    if (tid < NTILES_N)
        ps = g_psum[(size_t)row * NTILES_N + tid] * __expf(pm - M);
    red[tid] = ps; __syncthreads();
    #pragma unroll
    for (int s = 128; s > 0; s >>= 1) {
        if (tid < s) red[tid] += red[tid + s];
        __syncthreads();
    }

    if (tid == 0) {
        const int l = labels[row];
        if (l != -100) {
            const int sl = (l >= 0 && l < VOCAB) ? l : 0;
            g_nll[row] = logf(red[0]) + M - scores[(size_t)row * VOCAB + sl];
            g_cnt[row] = 1.f;
        } else {
            g_nll[row] = 0.f;
            g_cnt[row] = 0.f;
        }
        __threadfence();
        const unsigned old = atomicAdd(&g_done, 1u);
        last = (old == NTOK - 1) ? 1u : 0u;
    }
    __syncthreads();

    if (last) {
        __threadfence();                     // acquire side
        float s = 0.f, c = 0.f;
        for (int i = tid; i < NTOK; i += 256) { s += g_nll[i]; c += g_cnt[i]; }
        red[tid] = s; red2[tid] = c; __syncthreads();
        #pragma unroll
        for (int st = 128; st > 0; st >>= 1) {
            if (tid < st) { red[tid] += red[tid + st]; red2[tid] += red2[tid + st]; }
            __syncthreads();
        }
        if (tid == 0) {
            if (loss_out) loss_out[0] = red[0] / fmaxf(red2[0], 1.f);
            g_done = 0;                      // reset for next graph replay
        }
    }
}

// ---------------------------------------------------------------------------
extern "C" void kernel_launch(void* const* d_in, const int* in_sizes, int n_in,
                              void* d_out, int out_size) {
    const float* hidden = (const float*)d_in[0];
    const int*   labels = (const int*)d_in[1];
    const float* lnw    = (const float*)d_in[2];
    const float* W      = (const float*)d_in[3];

    float* out = (float*)d_out;
    long long extra = (long long)out_size - (long long)NTOK * (long long)VOCAB;
    if (extra < 0) extra = 0;
    float* scores   = out + extra;
    float* loss_ptr = (extra >= 1) ? out : nullptr;

    static int smem_set = 0;
    if (!smem_set) {
        cudaFuncSetAttribute(gemm_kernel,
                             cudaFuncAttributeMaxDynamicSharedMemorySize, SMEM_TOTAL);
        smem_set = 1;
    }

    prep_kernel<<<NTOK + WCVT_BLOCKS, 256>>>(hidden, lnw, W);
    gemm_kernel<<<dim3(NTILES_N, NTOK / BM), 256, SMEM_TOTAL>>>(scores);
    combine_loss_kernel<<<NTOK, 256>>>(scores, labels, loss_ptr);
}